// round 16
// baseline (speedup 1.0000x reference)
#include <cuda_runtime.h>
#include <cuda_fp16.h>
#include <math.h>

// ---------------------------------------------------------------------------
// Problem constants
// ---------------------------------------------------------------------------
#define BATCH 128
#define E_DIM 128
#define NHEAD 8
#define HW 256
#define MEM 8
#define DDIM 4096
#define BH 1024

#define OFF_H  ((size_t)0)
#define OFF_C  ((size_t)4194304)
#define OFF_K  ((size_t)8388608)
#define OFF_V  ((size_t)41943040)

typedef unsigned int u32;

// padded fp16 image: 18x18 rows x 64 ch = 324 rows x 128 B = 41472 B per kc
#define BPAD_ROWS 324
#define BPAD_BYTES (BPAD_ROWS * 128)

// ---------------------------------------------------------------------------
// Scratch (device globals — allocation-free; zero-init keeps never-written
// padded-image border rows zero forever)
// ---------------------------------------------------------------------------
__device__ float g_cc  [(size_t)BATCH * 640 * HW];
__device__ float g_q   [(size_t)BH * DDIM];
__device__ float g_outp[(size_t)BATCH * E_DIM * HW];

__device__ __align__(16) __half g_bin  [(size_t)BATCH * 4 * 20736];
__device__ __align__(16) __half g_battn[(size_t)BATCH * 2 * 20736];

// Pre-swizzled fp16 A tiles. tile = (mtile*9 + tap)*KC + kc ; 64x64 -> 8192 B.
__device__ __align__(16) __half g_wm[360 * 4096];
__device__ __align__(16) __half g_wp[108 * 4096];
__device__ __align__(16) __half g_wo[ 36 * 4096];

__device__ __forceinline__ float sigmoidf_(float x) { return 1.0f / (1.0f + expf(-x)); }

#define SW128(o) ((o) ^ (((o) >> 3) & 0x70))

__device__ __forceinline__ u32 smem_u32(const void* p) {
    u32 a;
    asm("{ .reg .u64 t; cvta.to.shared.u64 t, %1; cvt.u32.u64 %0, t; }" : "=r"(a) : "l"(p));
    return a;
}

__device__ __forceinline__ void ldm_x4(u32* r, u32 addr) {
    asm volatile("ldmatrix.sync.aligned.m8n8.x4.shared.b16 {%0,%1,%2,%3}, [%4];"
        : "=r"(r[0]), "=r"(r[1]), "=r"(r[2]), "=r"(r[3]) : "r"(addr));
}

__device__ __forceinline__ void mma_f16(float* c, const u32* a, u32 b0, u32 b1) {
    asm volatile("mma.sync.aligned.m16n8k16.row.col.f32.f16.f16.f32 "
        "{%0,%1,%2,%3}, {%4,%5,%6,%7}, {%8,%9}, {%0,%1,%2,%3};"
        : "+f"(c[0]), "+f"(c[1]), "+f"(c[2]), "+f"(c[3])
        : "r"(a[0]), "r"(a[1]), "r"(a[2]), "r"(a[3]), "r"(b0), "r"(b1));
}

__device__ __forceinline__ void cp16(u32 dst, const void* src) {
    asm volatile("cp.async.cg.shared.global [%0], [%1], 16;"
                 :: "r"(dst), "l"(src) : "memory");
}
#define CP_COMMIT() asm volatile("cp.async.commit_group;" ::: "memory")
#define CP_WAIT0()  asm volatile("cp.async.wait_group 0;"  ::: "memory")

// ---------------------------------------------------------------------------
// Stream/event resources (static init — allocation-free in kernel_launch)
// ---------------------------------------------------------------------------
struct OverlapRes {
    cudaStream_t sB;
    cudaEvent_t  evFork, evProj, evPrepM, evJoin;
    OverlapRes() {
        cudaStreamCreateWithFlags(&sB, cudaStreamNonBlocking);
        cudaEventCreateWithFlags(&evFork,  cudaEventDisableTiming);
        cudaEventCreateWithFlags(&evProj,  cudaEventDisableTiming);
        cudaEventCreateWithFlags(&evPrepM, cudaEventDisableTiming);
        cudaEventCreateWithFlags(&evJoin,  cudaEventDisableTiming);
    }
};
static OverlapRes g_res;

// ---------------------------------------------------------------------------
// KV shift (dependency-free): ret_k[m<7] = concat_k[m+1] + pos_w[m];
//                             ret_v[m<7] = concat_v[m+1].   All float4.
// ---------------------------------------------------------------------------
__global__ void __launch_bounds__(256)
shift_kv(const float* __restrict__ concat_k, const float* __restrict__ concat_v,
         const float* __restrict__ pos_w,
         float* __restrict__ ret_k, float* __restrict__ ret_v)
{
    const u32 t = blockIdx.x * 256 + threadIdx.x;   // < 1024*7*1024
    const int d4 = (int)(t & 1023);                 // float4 index within D
    const u32 r  = t >> 10;
    const int m  = (int)(r % 7);
    const int bh = (int)(r / 7);
    const int h  = bh & 7;

    const size_t src = ((size_t)bh * MEM + (m + 1)) * 1024 + d4;   // float4 units
    const size_t dst = ((size_t)bh * MEM + m) * 1024 + d4;

    float4 kv = ((const float4*)concat_k)[src];
    const float4 pv = ((const float4*)pos_w)[(size_t)(m * 8 + h) * 1024 + d4];
    kv.x += pv.x; kv.y += pv.y; kv.z += pv.z; kv.w += pv.w;
    ((float4*)ret_k)[dst] = kv;
    ((float4*)ret_v)[dst] = ((const float4*)concat_v)[src];
}

// ---------------------------------------------------------------------------
// Input prep: fp32 (input | h_cur) -> padded fp16 images in gmem.
// ---------------------------------------------------------------------------
__global__ void __launch_bounds__(256)
prep_in(const float* __restrict__ input, const float* __restrict__ h_cur)
{
    const int kc = blockIdx.x, b = blockIdx.y;
    const int tid = threadIdx.x;
    const float* cb = (kc < 2) ? input + ((size_t)b * 128 + kc * 64) * 256
                               : h_cur + ((size_t)b * 128 + (kc - 2) * 64) * 256;
    char* dst = (char*)g_bin + (size_t)(b * 4 + kc) * BPAD_BYTES;

    const int padw = ((tid >> 4) + 1) * 18 + (tid & 15) + 1;
    const u32 rowb = (u32)(padw * 128);
    const u32 rswz = (u32)((padw & 7) << 4);
#pragma unroll
    for (int gg = 0; gg < 8; gg++) {
        float v[8];
#pragma unroll
        for (int j = 0; j < 8; j++)
            v[j] = __ldg(cb + (size_t)(gg * 8 + j) * 256 + tid);
        u32 ph[4];
#pragma unroll
        for (int j = 0; j < 4; j++) {
            const __half2 hh = __floats2half2_rn(v[2*j], v[2*j+1]);
            ph[j] = *(const u32*)&hh;
        }
        *(uint4*)(dst + rowb + ((u32)(gg * 16) ^ rswz)) = make_uint4(ph[0], ph[1], ph[2], ph[3]);
    }
}

// ---------------------------------------------------------------------------
// Weight prep: fp32 [oc][CIN][9] -> swizzled fp16 64x64 K-major tiles
// ---------------------------------------------------------------------------
template<int WSEL>
__global__ void __launch_bounds__(256)
prep_w(const float* __restrict__ w, int ntiles, int KC)
{
    const int idx = blockIdx.x * 256 + threadIdx.x;
    if (idx >= ntiles * 2048) return;
    const int tile = idx >> 11, r = idx & 2047, row = r >> 5, kp = r & 31;
    const int kc = tile % KC, t2 = tile / KC, tap = t2 % 9, mtile = t2 / 9;
    const int CIN = KC * 64;
    const int oc  = mtile * 64 + row;
    const int cin = kc * 64 + kp * 2;
    const size_t wb = ((size_t)oc * CIN + cin) * 9 + tap;
    const __half2 hh = __floats2half2_rn(w[wb], w[wb + 9]);
    const u32 off = SW128((u32)(row * 128 + kp * 4));
    __half* hi = (WSEL == 0) ? g_wm : (WSEL == 1) ? g_wp : g_wo;
    *(u32*)((char*)hi + (size_t)tile * 8192 + off) = *(const u32*)&hh;
}

// ---------------------------------------------------------------------------
// Epilogue store of a float2 (two px) for one output channel
// ---------------------------------------------------------------------------
template<int OUTSEL>
__device__ __forceinline__ void store2(int ocg, int px, float v0, float v1, int b,
                                       const float* __restrict__ resid,
                                       const float* __restrict__ pos_w,
                                       float* __restrict__ d_out)
{
    if (OUTSEL == 0) {
        *(float2*)(g_cc + ((size_t)b * 640 + ocg) * 256 + px) = make_float2(v0, v1);
    } else if (OUTSEL == 2) {
        const float2 r = *(const float2*)(resid + ((size_t)b * 128 + ocg) * 256 + px);
        *(float2*)(g_outp + ((size_t)b * 128 + ocg) * 256 + px) =
            make_float2(v0 + r.x, v1 + r.y);
    } else {
        const int h = ocg / 48, rr = ocg % 48, grp = rr / 16, c = rr % 16;
        const size_t bh = (size_t)b * 8 + h;
        const size_t d0 = (size_t)c * 256 + px;
        if (grp == 0) {
            const float2 pw = *(const float2*)(pos_w + (size_t)7 * 32768 + (size_t)h * 4096 + d0);
            *(float2*)(d_out + OFF_K + (bh * 8 + 7) * 4096 + d0) =
                make_float2(v0 + pw.x, v1 + pw.y);
        } else if (grp == 1) {
            *(float2*)(g_q + bh * 4096 + d0) = make_float2(v0 * 0.015625f, v1 * 0.015625f);
        } else {
            *(float2*)(d_out + OFF_V + (bh * 8 + 7) * 4096 + d0) = make_float2(v0, v1);
        }
    }
}

// ---------------------------------------------------------------------------
// Implicit-GEMM 3x3 conv (identical to R13 best)
// ---------------------------------------------------------------------------
#define SB0 16384
#define SB1 57856
#define CONV_SMEM 99328

template<int KC, int OUTSEL>
__global__ void __launch_bounds__(256, 2)
conv_mma(const __half* __restrict__ whi,
         const char* __restrict__ ball, int bstride,
         const float* __restrict__ bias, const float* __restrict__ resid,
         const float* __restrict__ pos_w, float* __restrict__ d_out)
{
    extern __shared__ char smem[];
    const int b     = blockIdx.y;
    const int mtile = blockIdx.x;
    const int tid   = threadIdx.x;
    const int wid   = tid >> 5;
    const int lane  = tid & 31;
    const u32 sbase = smem_u32(smem);

    const int mrow  = (wid & 1) * 32;
    const int nbase = (wid >> 1) * 64;

    const int sel = lane >> 3, r8 = lane & 7;
    const int ar0  = mrow + r8 + ((sel & 1) << 3);
    const int ar1  = ar0 + 16;
    const u32 akad = (u32)((sel >> 1) << 4);
    const u32 ao0b = (u32)(ar0 * 128);
    const u32 ao1b = (u32)(ar1 * 128);
    const u32 asz0 = (u32)((ar0 & 7) << 4);
    const u32 asz1 = (u32)((ar1 & 7) << 4);
    const int pxr  = nbase + r8 + ((sel >> 1) << 3);
    const u32 bkad = (u32)((sel & 1) << 4);
    const int pad00 = ((pxr >> 4) + 1) * 18 + ((pxr & 15) + 1);

    float acc0[32], acc1[32];
#pragma unroll
    for (int i = 0; i < 32; i++) { acc0[i] = 0.0f; acc1[i] = 0.0f; }

    auto bimg = [&](int kc) {
        return ball + ((size_t)b * bstride + kc) * BPAD_BYTES;
    };
    auto issueA = [&](int tile, int buf) {
        const char* gh = (const char*)whi + (size_t)tile * 8192;
        const u32 dh = sbase + (u32)(buf << 13);
        const u32 o = (u32)(tid * 16);
        cp16(dh + o, gh + o);
        cp16(dh + o + 4096, gh + o + 4096);
    };

    {
        const char* src = bimg(0);
        for (u32 o = (u32)tid * 16; o < BPAD_BYTES; o += 4096)
            cp16(sbase + SB0 + o, src + o);
        issueA((mtile * 9) * KC, 0);
        CP_COMMIT();
    }

    int g = 0, bbuf = 0;
    for (int kc = 0; kc < KC; kc++) {
        const u32 Bb = sbase + (bbuf ? SB1 : SB0);
        const u32 Bn = sbase + (bbuf ? SB0 : SB1);
        const char* nsrc = (kc + 1 < KC) ? bimg(kc + 1) : nullptr;

        for (int tap = 0; tap < 9; tap++) {
            const int s = g & 1;
            CP_WAIT0();
            __syncthreads();

            {
                int ntap = tap + 1, nkc = kc;
                if (ntap == 9) { ntap = 0; nkc = kc + 1; }
                if (nkc < KC)
                    issueA((mtile * 9 + ntap) * KC + nkc, s ^ 1);
            }
            if (nsrc && tap < 8) {
                const u32 c0 = (u32)tap * 5184;
                for (u32 o = c0 + (u32)tid * 16; o < c0 + 5184; o += 4096)
                    cp16(Bn + o, nsrc + o);
            }
            CP_COMMIT();

            const int toff = (tap / 3 - 1) * 18 + (tap % 3 - 1);
            const u32 Ab = sbase + (u32)(s << 13);
#pragma unroll
            for (int q = 0; q < 4; q++) {
                const u32 ka = (u32)(q * 32) + akad;
                u32 a0[4], a1[4];
                ldm_x4(a0, Ab + ao0b + (ka ^ asz0));
                ldm_x4(a1, Ab + ao1b + (ka ^ asz1));
                const u32 kb = (u32)(q * 32) + bkad;
#pragma unroll
                for (int jj = 0; jj < 4; jj++) {
                    const int pr = pad00 + jj * 18 + toff;
                    const u32 bo = (u32)(pr * 128) + (kb ^ ((u32)(pr & 7) << 4));
                    u32 bh[4];
                    ldm_x4(bh, Bb + bo);
                    float* c0 = acc0 + jj * 8;
                    mma_f16(c0,     a0, bh[0], bh[1]);  mma_f16(c0 + 4, a0, bh[2], bh[3]);
                    float* c1 = acc1 + jj * 8;
                    mma_f16(c1,     a1, bh[0], bh[1]);  mma_f16(c1 + 4, a1, bh[2], bh[3]);
                }
            }
            g++;
        }
        bbuf ^= 1;
    }

    const int g2 = lane >> 2, qp = lane & 3;
#pragma unroll
    for (int mt = 0; mt < 2; mt++) {
        const float* am = mt ? acc1 : acc0;
        const int ocg0 = mtile * 64 + mrow + mt * 16 + g2;
        const int ocg1 = ocg0 + 8;
        const float bv0 = __ldg(bias + ocg0);
        const float bv1 = __ldg(bias + ocg1);
#pragma unroll
        for (int t = 0; t < 8; t++) {
            const int px = nbase + t * 8 + qp * 2;
            const float* c = am + t * 4;
            store2<OUTSEL>(ocg0, px, c[0] + bv0, c[1] + bv0, b, resid, pos_w, d_out);
            store2<OUTSEL>(ocg1, px, c[2] + bv1, c[3] + bv1, b, resid, pos_w, d_out);
        }
    }
}

// ---------------------------------------------------------------------------
// LSTM gate fusion (float4)
// ---------------------------------------------------------------------------
__global__ void __launch_bounds__(256)
gates_kernel(const float* __restrict__ c_cur, float* __restrict__ d_out)
{
    const u32 f = blockIdx.x * 256 + threadIdx.x;
    const int b  = (int)(f >> 13);
    const int r4 = (int)(f & 8191);
    const float4* cc = (const float4*)(g_cc + (size_t)b * 640 * HW);
    const float4 ci = cc[r4];
    const float4 cf = cc[r4 + 8192];
    const float4 cg = cc[r4 + 24576];
    const float4 cu = ((const float4*)c_cur)[f];
    float4 o;
    o.x = sigmoidf_(cf.x) * cu.x + sigmoidf_(ci.x) * tanhf(cg.x);
    o.y = sigmoidf_(cf.y) * cu.y + sigmoidf_(ci.y) * tanhf(cg.y);
    o.z = sigmoidf_(cf.z) * cu.z + sigmoidf_(ci.z) * tanhf(cg.z);
    o.w = sigmoidf_(cf.w) * cu.w + sigmoidf_(ci.w) * tanhf(cg.w);
    ((float4*)(d_out + OFF_C))[f] = o;
}

// ---------------------------------------------------------------------------
// Small attention: scores from ret_k (pos already included, all 8 slots),
// softmax, output from ret_v, fp16-image write. No shift stores.
// ---------------------------------------------------------------------------
__global__ void __launch_bounds__(256)
attn_small(const unsigned int* __restrict__ mask, const float* __restrict__ pos_b,
           const float* __restrict__ ret_k, const float* __restrict__ ret_v)
{
    const int bh  = blockIdx.x;
    const int h   = bh & 7;
    const int tid = threadIdx.x;
    const int wid = tid >> 5, lane = tid & 31;

    float4 q4[4];
#pragma unroll
    for (int j = 0; j < 4; j++)
        q4[j] = ((const float4*)(g_q + (size_t)bh * DDIM))[j * 256 + tid];

    __shared__ float red2[8][MEM];
    __shared__ float w8[MEM];

    float part[MEM];
#pragma unroll
    for (int m = 0; m < MEM; m++) {
        const float4* ks = (const float4*)(ret_k + ((size_t)bh * MEM + m) * DDIM);
        float p = 0.0f;
#pragma unroll
        for (int j = 0; j < 4; j++) {
            const float4 kv = ks[j * 256 + tid];
            p = fmaf(q4[j].x, kv.x, p);
            p = fmaf(q4[j].y, kv.y, p);
            p = fmaf(q4[j].z, kv.z, p);
            p = fmaf(q4[j].w, kv.w, p);
        }
        part[m] = p;
    }

#pragma unroll
    for (int m = 0; m < MEM; m++)
#pragma unroll
        for (int off = 16; off > 0; off >>= 1)
            part[m] += __shfl_down_sync(0xffffffffu, part[m], off);
    if (lane == 0)
#pragma unroll
        for (int m = 0; m < MEM; m++) red2[wid][m] = part[m];
    __syncthreads();

    if (tid == 0) {
        float sc[MEM];
        float mx = -1e30f;
#pragma unroll
        for (int m = 0; m < MEM; m++) {
            float t = 0.0f;
#pragma unroll
            for (int w = 0; w < 8; w++) t += red2[w][m];
            float mf = (m == 7) ? 3.0f : (mask[bh * MEM + m] != 0u ? -1e30f : 0.0f);
            sc[m] = mf + t + pos_b[m * NHEAD + h];
            mx = fmaxf(mx, sc[m]);
        }
        float ssum = 0.0f;
#pragma unroll
        for (int m = 0; m < MEM; m++) { sc[m] = expf(sc[m] - mx); ssum += sc[m]; }
        const float inv = 1.0f / ssum;
#pragma unroll
        for (int m = 0; m < MEM; m++) w8[m] = sc[m] * inv;
    }
    __syncthreads();

    float wl[MEM];
#pragma unroll
    for (int m = 0; m < MEM; m++) wl[m] = w8[m];

    float accv[16];
#pragma unroll
    for (int i = 0; i < 16; i++) {
        const int idx = i * 256 + tid;
        float acc = 0.0f;
#pragma unroll
        for (int m = 0; m < MEM; m++)
            acc = fmaf(wl[m], ret_v[((size_t)bh * MEM + m) * DDIM + idx], acc);
        accv[i] = acc;
    }

    u32 ph[8];
#pragma unroll
    for (int j = 0; j < 8; j++) {
        const __half2 hh = __floats2half2_rn(accv[2*j], accv[2*j+1]);
        ph[j] = *(const u32*)&hh;
    }
    const int b  = bh >> 3;
    const int kc = h >> 2;
    char* dst = (char*)g_battn + (size_t)(b * 2 + kc) * BPAD_BYTES;
    const int padw = ((tid >> 4) + 1) * 18 + (tid & 15) + 1;
    const u32 rowb = (u32)(padw * 128);
    const u32 rswz = (u32)((padw & 7) << 4);
    const u32 coff = (u32)((h & 3) * 32);
    *(uint4*)(dst + rowb + ((coff +  0) ^ rswz)) = make_uint4(ph[0], ph[1], ph[2], ph[3]);
    *(uint4*)(dst + rowb + ((coff + 16) ^ rswz)) = make_uint4(ph[4], ph[5], ph[6], ph[7]);
}

// ---------------------------------------------------------------------------
// Fused LayerNorm + final LSTM update (float4)
// ---------------------------------------------------------------------------
__global__ void __launch_bounds__(512)
ln_final(const float* __restrict__ norm_w, const float* __restrict__ norm_b,
         float* __restrict__ d_out)
{
    const int b   = blockIdx.x;
    const int tid = threadIdx.x;
    const float4* p4 = (const float4*)(g_outp + (size_t)b * 32768);

    float s = 0.0f, s2 = 0.0f;
    for (int f = tid; f < 8192; f += 512) {
        const float4 v = p4[f];
        s += v.x + v.y + v.z + v.w;
        s2 = fmaf(v.x, v.x, s2); s2 = fmaf(v.y, v.y, s2);
        s2 = fmaf(v.z, v.z, s2); s2 = fmaf(v.w, v.w, s2);
    }
#pragma unroll
    for (int off = 16; off > 0; off >>= 1) {
        s  += __shfl_down_sync(0xffffffffu, s, off);
        s2 += __shfl_down_sync(0xffffffffu, s2, off);
    }
    __shared__ float rs_[16], rs2_[16];
    __shared__ float sh_mu, sh_rs;
    if ((tid & 31) == 0) { rs_[tid >> 5] = s; rs2_[tid >> 5] = s2; }
    __syncthreads();
    if (tid == 0) {
        float ts = 0.0f, ts2 = 0.0f;
#pragma unroll
        for (int w = 0; w < 16; w++) { ts += rs_[w]; ts2 += rs2_[w]; }
        const float mu  = ts * (1.0f / 32768.0f);
        const float var = ts2 * (1.0f / 32768.0f) - mu * mu;
        sh_mu = mu;
        sh_rs = rsqrtf(var + 1e-5f);
    }
    __syncthreads();

    const float mu = sh_mu, rs = sh_rs;
    const float4* cc4 = (const float4*)(g_cc + (size_t)b * 640 * HW);
    const float4* nw4 = (const float4*)norm_w;
    const float4* nb4 = (const float4*)norm_b;
    float4* dc = (float4*)(d_out + OFF_C + (size_t)b * 32768);
    float4* dh = (float4*)(d_out + OFF_H + (size_t)b * 32768);
    for (int f = tid; f < 8192; f += 512) {
        const float4 pv = p4[f];
        const float4 wv = nw4[f], bv = nb4[f];
        const float4 ov = cc4[f + 16384];
        const float4 av = cc4[f + 32768];
        float4 cv = dc[f];
        float4 hv;
        { const float ln = (pv.x - mu) * rs * wv.x + bv.x;
          cv.x += sigmoidf_(av.x) * tanhf(ln); hv.x = sigmoidf_(ov.x) * tanhf(cv.x); }
        { const float ln = (pv.y - mu) * rs * wv.y + bv.y;
          cv.y += sigmoidf_(av.y) * tanhf(ln); hv.y = sigmoidf_(ov.y) * tanhf(cv.y); }
        { const float ln = (pv.z - mu) * rs * wv.z + bv.z;
          cv.z += sigmoidf_(av.z) * tanhf(ln); hv.z = sigmoidf_(ov.z) * tanhf(cv.z); }
        { const float ln = (pv.w - mu) * rs * wv.w + bv.w;
          cv.w += sigmoidf_(av.w) * tanhf(ln); hv.w = sigmoidf_(ov.w) * tanhf(cv.w); }
        dc[f] = cv;
        dh[f] = hv;
    }
}

// ---------------------------------------------------------------------------
// Launch:
//   s0: [evFork] -> prep_w(proj) -> prep_in -> proj -> [evProj]
//       -> (wait evPrepM) -> main conv -> gates -> (wait evJoin) -> ln
//   sB: wait(evFork) -> shift_kv -> prep_w(out) -> prep_w(main) -> [evPrepM]
//       -> (wait evProj) -> attn_small -> out conv -> [evJoin]
// ---------------------------------------------------------------------------
extern "C" void kernel_launch(void* const* d_in, const int* in_sizes, int n_in,
                              void* d_out_v, int out_size)
{
    const float* input    = (const float*)d_in[0];
    const float* h_cur    = (const float*)d_in[1];
    const float* c_cur    = (const float*)d_in[2];
    const float* concat_k = (const float*)d_in[3];
    const float* concat_v = (const float*)d_in[4];
    const unsigned int* attn_mask = (const unsigned int*)d_in[5];
    const float* main_w   = (const float*)d_in[6];
    const float* main_b   = (const float*)d_in[7];
    const float* proj_w   = (const float*)d_in[8];
    const float* proj_b   = (const float*)d_in[9];
    const float* out_w    = (const float*)d_in[10];
    const float* out_b    = (const float*)d_in[11];
    const float* norm_w   = (const float*)d_in[12];
    const float* norm_b   = (const float*)d_in[13];
    const float* pos_w    = (const float*)d_in[14];
    const float* pos_b    = (const float*)d_in[15];
    float* d_out = (float*)d_out_v;

    cudaFuncSetAttribute(conv_mma<4,0>, cudaFuncAttributeMaxDynamicSharedMemorySize, CONV_SMEM);
    cudaFuncSetAttribute(conv_mma<2,1>, cudaFuncAttributeMaxDynamicSharedMemorySize, CONV_SMEM);
    cudaFuncSetAttribute(conv_mma<2,2>, cudaFuncAttributeMaxDynamicSharedMemorySize, CONV_SMEM);

    __half *wm, *wp, *wo;
    char *bin_p, *battn_p;
    cudaGetSymbolAddress((void**)&wm, g_wm);
    cudaGetSymbolAddress((void**)&wp, g_wp);
    cudaGetSymbolAddress((void**)&wo, g_wo);
    cudaGetSymbolAddress((void**)&bin_p, g_bin);
    cudaGetSymbolAddress((void**)&battn_p, g_battn);

    cudaStream_t s0 = 0;
    cudaStream_t sB = g_res.sB;

    // ---- fork (must originate in the capture stream) ----
    cudaEventRecord(g_res.evFork, s0);
    cudaStreamWaitEvent(sB, g_res.evFork, 0);

    // ---- sB: dependency-free KV shift + weight preps for out/main ----
    shift_kv<<<28672, 256, 0, sB>>>(concat_k, concat_v, pos_w,
                                    d_out + OFF_K, d_out + OFF_V);
    prep_w<2><<<( 36 * 2048) / 256, 256, 0, sB>>>(out_w, 36, 2);
    prep_w<0><<<(360 * 2048) / 256, 256, 0, sB>>>(main_w, 360, 4);
    cudaEventRecord(g_res.evPrepM, sB);

    // ---- s0: proj path ----
    prep_w<1><<<(108 * 2048) / 256, 256, 0, s0>>>(proj_w, 108, 2);
    prep_in<<<dim3(4, BATCH), 256, 0, s0>>>(input, h_cur);
    conv_mma<2,1><<<dim3(6, BATCH), 256, CONV_SMEM, s0>>>(
        wp, bin_p, 4, proj_b, nullptr, pos_w, d_out);
    cudaEventRecord(g_res.evProj, s0);

    // ---- sB: attention + out conv (needs proj outputs + shifted kv) ----
    cudaStreamWaitEvent(sB, g_res.evProj, 0);
    attn_small<<<BH, 256, 0, sB>>>(attn_mask, pos_b, d_out + OFF_K, d_out + OFF_V);
    conv_mma<2,2><<<dim3(2, BATCH), 256, CONV_SMEM, sB>>>(
        wo, battn_p, 2, out_b, input, nullptr, d_out);
    cudaEventRecord(g_res.evJoin, sB);

    // ---- s0: main conv + gates ----
    cudaStreamWaitEvent(s0, g_res.evPrepM, 0);
    conv_mma<4,0><<<dim3(10, BATCH), 256, CONV_SMEM, s0>>>(
        wm, bin_p, 4, main_b, nullptr, nullptr, d_out);
    gates_kernel<<<4096, 256, 0, s0>>>(c_cur, d_out);

    // ---- join + final ----
    cudaStreamWaitEvent(s0, g_res.evJoin, 0);
    ln_final<<<BATCH, 512, 0, s0>>>(norm_w, norm_b, d_out);
}

// round 17
// speedup vs baseline: 1.1046x; 1.1046x over previous
#include <cuda_runtime.h>
#include <cuda_fp16.h>
#include <math.h>

// ---------------------------------------------------------------------------
// Problem constants
// ---------------------------------------------------------------------------
#define BATCH 128
#define E_DIM 128
#define NHEAD 8
#define HW 256
#define MEM 8
#define DDIM 4096
#define BH 1024

#define OFF_H  ((size_t)0)
#define OFF_C  ((size_t)4194304)
#define OFF_K  ((size_t)8388608)
#define OFF_V  ((size_t)41943040)

typedef unsigned int u32;

// padded fp16 image: 18x18 rows x 64 ch = 324 rows x 128 B = 41472 B per kc
#define BPAD_ROWS 324
#define BPAD_BYTES (BPAD_ROWS * 128)

// ---------------------------------------------------------------------------
// Scratch (device globals — allocation-free; zero-init keeps never-written
// padded-image border rows zero forever)
// ---------------------------------------------------------------------------
__device__ float g_cc  [(size_t)BATCH * 640 * HW];
__device__ float g_q   [(size_t)BH * DDIM];
__device__ float g_outp[(size_t)BATCH * E_DIM * HW];

__device__ __align__(16) __half g_bin  [(size_t)BATCH * 4 * 20736];
__device__ __align__(16) __half g_battn[(size_t)BATCH * 2 * 20736];

// Pre-swizzled fp16 A tiles. tile = (mtile*9 + tap)*KC + kc ; 64x64 -> 8192 B.
__device__ __align__(16) __half g_wm[360 * 4096];
__device__ __align__(16) __half g_wp[108 * 4096];
__device__ __align__(16) __half g_wo[ 36 * 4096];

__device__ __forceinline__ float sigmoidf_(float x) { return 1.0f / (1.0f + expf(-x)); }

#define SW128(o) ((o) ^ (((o) >> 3) & 0x70))

__device__ __forceinline__ u32 smem_u32(const void* p) {
    u32 a;
    asm("{ .reg .u64 t; cvta.to.shared.u64 t, %1; cvt.u32.u64 %0, t; }" : "=r"(a) : "l"(p));
    return a;
}

__device__ __forceinline__ void ldm_x4(u32* r, u32 addr) {
    asm volatile("ldmatrix.sync.aligned.m8n8.x4.shared.b16 {%0,%1,%2,%3}, [%4];"
        : "=r"(r[0]), "=r"(r[1]), "=r"(r[2]), "=r"(r[3]) : "r"(addr));
}

__device__ __forceinline__ void mma_f16(float* c, const u32* a, u32 b0, u32 b1) {
    asm volatile("mma.sync.aligned.m16n8k16.row.col.f32.f16.f16.f32 "
        "{%0,%1,%2,%3}, {%4,%5,%6,%7}, {%8,%9}, {%0,%1,%2,%3};"
        : "+f"(c[0]), "+f"(c[1]), "+f"(c[2]), "+f"(c[3])
        : "r"(a[0]), "r"(a[1]), "r"(a[2]), "r"(a[3]), "r"(b0), "r"(b1));
}

__device__ __forceinline__ void cp16(u32 dst, const void* src) {
    asm volatile("cp.async.cg.shared.global [%0], [%1], 16;"
                 :: "r"(dst), "l"(src) : "memory");
}
#define CP_COMMIT() asm volatile("cp.async.commit_group;" ::: "memory")
#define CP_WAIT0()  asm volatile("cp.async.wait_group 0;"  ::: "memory")

// ---------------------------------------------------------------------------
// Stream/event resources (static init — allocation-free in kernel_launch)
// ---------------------------------------------------------------------------
struct OverlapRes {
    cudaStream_t sB;
    cudaEvent_t  evFork, evJoin;
    OverlapRes() {
        cudaStreamCreateWithFlags(&sB, cudaStreamNonBlocking);
        cudaEventCreateWithFlags(&evFork, cudaEventDisableTiming);
        cudaEventCreateWithFlags(&evJoin, cudaEventDisableTiming);
    }
};
static OverlapRes g_res;

// ---------------------------------------------------------------------------
// Input prep: fp32 (input | h_cur) -> padded fp16 images in gmem.
// Regridded for latency hiding: blockIdx.x = kc*4 + quarter; each thread
// handles 2 channel-groups (16 channels) for its pixel.
// ---------------------------------------------------------------------------
__global__ void __launch_bounds__(256)
prep_in(const float* __restrict__ input, const float* __restrict__ h_cur)
{
    const int kc  = blockIdx.x >> 2;
    const int gq  = blockIdx.x & 3;        // quarter: gg = 2*gq, 2*gq+1
    const int b   = blockIdx.y;
    const int tid = threadIdx.x;
    const float* cb = (kc < 2) ? input + ((size_t)b * 128 + kc * 64) * 256
                               : h_cur + ((size_t)b * 128 + (kc - 2) * 64) * 256;
    char* dst = (char*)g_bin + (size_t)(b * 4 + kc) * BPAD_BYTES;

    const int padw = ((tid >> 4) + 1) * 18 + (tid & 15) + 1;
    const u32 rowb = (u32)(padw * 128);
    const u32 rswz = (u32)((padw & 7) << 4);
#pragma unroll
    for (int t = 0; t < 2; t++) {
        const int gg = gq * 2 + t;
        float v[8];
#pragma unroll
        for (int j = 0; j < 8; j++)
            v[j] = __ldg(cb + (size_t)(gg * 8 + j) * 256 + tid);
        u32 ph[4];
#pragma unroll
        for (int j = 0; j < 4; j++) {
            const __half2 hh = __floats2half2_rn(v[2*j], v[2*j+1]);
            ph[j] = *(const u32*)&hh;
        }
        *(uint4*)(dst + rowb + ((u32)(gg * 16) ^ rswz)) = make_uint4(ph[0], ph[1], ph[2], ph[3]);
    }
}

// ---------------------------------------------------------------------------
// Weight prep: fp32 [oc][CIN][9] -> swizzled fp16 64x64 K-major tiles
// ---------------------------------------------------------------------------
template<int WSEL>
__global__ void __launch_bounds__(256)
prep_w(const float* __restrict__ w, int ntiles, int KC)
{
    const int idx = blockIdx.x * 256 + threadIdx.x;
    if (idx >= ntiles * 2048) return;
    const int tile = idx >> 11, r = idx & 2047, row = r >> 5, kp = r & 31;
    const int kc = tile % KC, t2 = tile / KC, tap = t2 % 9, mtile = t2 / 9;
    const int CIN = KC * 64;
    const int oc  = mtile * 64 + row;
    const int cin = kc * 64 + kp * 2;
    const size_t wb = ((size_t)oc * CIN + cin) * 9 + tap;
    const __half2 hh = __floats2half2_rn(w[wb], w[wb + 9]);
    const u32 off = SW128((u32)(row * 128 + kp * 4));
    __half* hi = (WSEL == 0) ? g_wm : (WSEL == 1) ? g_wp : g_wo;
    *(u32*)((char*)hi + (size_t)tile * 8192 + off) = *(const u32*)&hh;
}

// ---------------------------------------------------------------------------
// Epilogue store of a float2 (two px) for one output channel
// ---------------------------------------------------------------------------
template<int OUTSEL>
__device__ __forceinline__ void store2(int ocg, int px, float v0, float v1, int b,
                                       const float* __restrict__ resid,
                                       const float* __restrict__ pos_w,
                                       float* __restrict__ d_out)
{
    if (OUTSEL == 0) {
        *(float2*)(g_cc + ((size_t)b * 640 + ocg) * 256 + px) = make_float2(v0, v1);
    } else if (OUTSEL == 2) {
        const float2 r = *(const float2*)(resid + ((size_t)b * 128 + ocg) * 256 + px);
        *(float2*)(g_outp + ((size_t)b * 128 + ocg) * 256 + px) =
            make_float2(v0 + r.x, v1 + r.y);
    } else {
        const int h = ocg / 48, rr = ocg % 48, grp = rr / 16, c = rr % 16;
        const size_t bh = (size_t)b * 8 + h;
        const size_t d0 = (size_t)c * 256 + px;
        if (grp == 0) {
            const float2 pw = *(const float2*)(pos_w + (size_t)7 * 32768 + (size_t)h * 4096 + d0);
            *(float2*)(d_out + OFF_K + (bh * 8 + 7) * 4096 + d0) =
                make_float2(v0 + pw.x, v1 + pw.y);
        } else if (grp == 1) {
            *(float2*)(g_q + bh * 4096 + d0) = make_float2(v0 * 0.015625f, v1 * 0.015625f);
        } else {
            *(float2*)(d_out + OFF_V + (bh * 8 + 7) * 4096 + d0) = make_float2(v0, v1);
        }
    }
}

// ---------------------------------------------------------------------------
// Implicit-GEMM 3x3 conv (identical to R13 best)
// ---------------------------------------------------------------------------
#define SB0 16384
#define SB1 57856
#define CONV_SMEM 99328

template<int KC, int OUTSEL>
__global__ void __launch_bounds__(256, 2)
conv_mma(const __half* __restrict__ whi,
         const char* __restrict__ ball, int bstride,
         const float* __restrict__ bias, const float* __restrict__ resid,
         const float* __restrict__ pos_w, float* __restrict__ d_out)
{
    extern __shared__ char smem[];
    const int b     = blockIdx.y;
    const int mtile = blockIdx.x;
    const int tid   = threadIdx.x;
    const int wid   = tid >> 5;
    const int lane  = tid & 31;
    const u32 sbase = smem_u32(smem);

    const int mrow  = (wid & 1) * 32;
    const int nbase = (wid >> 1) * 64;

    const int sel = lane >> 3, r8 = lane & 7;
    const int ar0  = mrow + r8 + ((sel & 1) << 3);
    const int ar1  = ar0 + 16;
    const u32 akad = (u32)((sel >> 1) << 4);
    const u32 ao0b = (u32)(ar0 * 128);
    const u32 ao1b = (u32)(ar1 * 128);
    const u32 asz0 = (u32)((ar0 & 7) << 4);
    const u32 asz1 = (u32)((ar1 & 7) << 4);
    const int pxr  = nbase + r8 + ((sel >> 1) << 3);
    const u32 bkad = (u32)((sel & 1) << 4);
    const int pad00 = ((pxr >> 4) + 1) * 18 + ((pxr & 15) + 1);

    float acc0[32], acc1[32];
#pragma unroll
    for (int i = 0; i < 32; i++) { acc0[i] = 0.0f; acc1[i] = 0.0f; }

    auto bimg = [&](int kc) {
        return ball + ((size_t)b * bstride + kc) * BPAD_BYTES;
    };
    auto issueA = [&](int tile, int buf) {
        const char* gh = (const char*)whi + (size_t)tile * 8192;
        const u32 dh = sbase + (u32)(buf << 13);
        const u32 o = (u32)(tid * 16);
        cp16(dh + o, gh + o);
        cp16(dh + o + 4096, gh + o + 4096);
    };

    {
        const char* src = bimg(0);
        for (u32 o = (u32)tid * 16; o < BPAD_BYTES; o += 4096)
            cp16(sbase + SB0 + o, src + o);
        issueA((mtile * 9) * KC, 0);
        CP_COMMIT();
    }

    int g = 0, bbuf = 0;
    for (int kc = 0; kc < KC; kc++) {
        const u32 Bb = sbase + (bbuf ? SB1 : SB0);
        const u32 Bn = sbase + (bbuf ? SB0 : SB1);
        const char* nsrc = (kc + 1 < KC) ? bimg(kc + 1) : nullptr;

        for (int tap = 0; tap < 9; tap++) {
            const int s = g & 1;
            CP_WAIT0();
            __syncthreads();

            {
                int ntap = tap + 1, nkc = kc;
                if (ntap == 9) { ntap = 0; nkc = kc + 1; }
                if (nkc < KC)
                    issueA((mtile * 9 + ntap) * KC + nkc, s ^ 1);
            }
            if (nsrc && tap < 8) {
                const u32 c0 = (u32)tap * 5184;
                for (u32 o = c0 + (u32)tid * 16; o < c0 + 5184; o += 4096)
                    cp16(Bn + o, nsrc + o);
            }
            CP_COMMIT();

            const int toff = (tap / 3 - 1) * 18 + (tap % 3 - 1);
            const u32 Ab = sbase + (u32)(s << 13);
#pragma unroll
            for (int q = 0; q < 4; q++) {
                const u32 ka = (u32)(q * 32) + akad;
                u32 a0[4], a1[4];
                ldm_x4(a0, Ab + ao0b + (ka ^ asz0));
                ldm_x4(a1, Ab + ao1b + (ka ^ asz1));
                const u32 kb = (u32)(q * 32) + bkad;
#pragma unroll
                for (int jj = 0; jj < 4; jj++) {
                    const int pr = pad00 + jj * 18 + toff;
                    const u32 bo = (u32)(pr * 128) + (kb ^ ((u32)(pr & 7) << 4));
                    u32 bh[4];
                    ldm_x4(bh, Bb + bo);
                    float* c0 = acc0 + jj * 8;
                    mma_f16(c0,     a0, bh[0], bh[1]);  mma_f16(c0 + 4, a0, bh[2], bh[3]);
                    float* c1 = acc1 + jj * 8;
                    mma_f16(c1,     a1, bh[0], bh[1]);  mma_f16(c1 + 4, a1, bh[2], bh[3]);
                }
            }
            g++;
        }
        bbuf ^= 1;
    }

    const int g2 = lane >> 2, qp = lane & 3;
#pragma unroll
    for (int mt = 0; mt < 2; mt++) {
        const float* am = mt ? acc1 : acc0;
        const int ocg0 = mtile * 64 + mrow + mt * 16 + g2;
        const int ocg1 = ocg0 + 8;
        const float bv0 = __ldg(bias + ocg0);
        const float bv1 = __ldg(bias + ocg1);
#pragma unroll
        for (int t = 0; t < 8; t++) {
            const int px = nbase + t * 8 + qp * 2;
            const float* c = am + t * 4;
            store2<OUTSEL>(ocg0, px, c[0] + bv0, c[1] + bv0, b, resid, pos_w, d_out);
            store2<OUTSEL>(ocg1, px, c[2] + bv1, c[3] + bv1, b, resid, pos_w, d_out);
        }
    }
}

// ---------------------------------------------------------------------------
// Fused attention: float4 k-pass, scalar v-pass, fp16-image output
// (identical to R13 best)
// ---------------------------------------------------------------------------
__global__ void __launch_bounds__(256)
attn_fused(const float* __restrict__ concat_k, const float* __restrict__ concat_v,
           const unsigned int* __restrict__ mask,
           const float* __restrict__ pos_w, const float* __restrict__ pos_b,
           float* __restrict__ ret_k, float* __restrict__ ret_v)
{
    const int bh  = blockIdx.x;
    const int h   = bh & 7;
    const int tid = threadIdx.x;
    const int wid = tid >> 5, lane = tid & 31;

    float4 q4[4];
#pragma unroll
    for (int j = 0; j < 4; j++)
        q4[j] = ((const float4*)(g_q + (size_t)bh * DDIM))[j * 256 + tid];

    __shared__ float red2[8][MEM];
    __shared__ float w8[MEM];

    float part[MEM];
#pragma unroll
    for (int m = 0; m < MEM; m++) {
        const float4* ks = (const float4*)((m < 7)
            ? concat_k + ((size_t)bh * MEM + (m + 1)) * DDIM
            : ret_k    + ((size_t)bh * MEM + 7) * DDIM);
        const float4* pw = (const float4*)(pos_w + (size_t)m * 32768 + (size_t)h * DDIM);
        float4* rk = (float4*)(ret_k + ((size_t)bh * MEM + m) * DDIM);
        float p = 0.0f;
#pragma unroll
        for (int j = 0; j < 4; j++) {
            const int f = j * 256 + tid;
            float4 kv = ks[f];
            if (m < 7) {
                const float4 pv = pw[f];
                kv.x += pv.x; kv.y += pv.y; kv.z += pv.z; kv.w += pv.w;
                rk[f] = kv;
            }
            p = fmaf(q4[j].x, kv.x, p);
            p = fmaf(q4[j].y, kv.y, p);
            p = fmaf(q4[j].z, kv.z, p);
            p = fmaf(q4[j].w, kv.w, p);
        }
        part[m] = p;
    }

#pragma unroll
    for (int m = 0; m < MEM; m++)
#pragma unroll
        for (int off = 16; off > 0; off >>= 1)
            part[m] += __shfl_down_sync(0xffffffffu, part[m], off);
    if (lane == 0)
#pragma unroll
        for (int m = 0; m < MEM; m++) red2[wid][m] = part[m];
    __syncthreads();

    if (tid == 0) {
        float sc[MEM];
        float mx = -1e30f;
#pragma unroll
        for (int m = 0; m < MEM; m++) {
            float t = 0.0f;
#pragma unroll
            for (int w = 0; w < 8; w++) t += red2[w][m];
            float mf = (m == 7) ? 3.0f : (mask[bh * MEM + m] != 0u ? -1e30f : 0.0f);
            sc[m] = mf + t + pos_b[m * NHEAD + h];
            mx = fmaxf(mx, sc[m]);
        }
        float ssum = 0.0f;
#pragma unroll
        for (int m = 0; m < MEM; m++) { sc[m] = expf(sc[m] - mx); ssum += sc[m]; }
        const float inv = 1.0f / ssum;
#pragma unroll
        for (int m = 0; m < MEM; m++) w8[m] = sc[m] * inv;
    }
    __syncthreads();

    float wl[MEM];
#pragma unroll
    for (int m = 0; m < MEM; m++) wl[m] = w8[m];

    float accv[16];
#pragma unroll
    for (int i = 0; i < 16; i++) {
        const int idx = i * 256 + tid;
        float acc = 0.0f;
#pragma unroll
        for (int m = 0; m < MEM; m++) {
            float vv;
            if (m < 7) {
                vv = concat_v[((size_t)bh * MEM + (m + 1)) * DDIM + idx];
                ret_v[((size_t)bh * MEM + m) * DDIM + idx] = vv;
            } else {
                vv = ret_v[((size_t)bh * MEM + 7) * DDIM + idx];
            }
            acc = fmaf(wl[m], vv, acc);
        }
        accv[i] = acc;
    }

    u32 ph[8];
#pragma unroll
    for (int j = 0; j < 8; j++) {
        const __half2 hh = __floats2half2_rn(accv[2*j], accv[2*j+1]);
        ph[j] = *(const u32*)&hh;
    }
    const int b  = bh >> 3;
    const int kc = h >> 2;
    char* dst = (char*)g_battn + (size_t)(b * 2 + kc) * BPAD_BYTES;
    const int padw = ((tid >> 4) + 1) * 18 + (tid & 15) + 1;
    const u32 rowb = (u32)(padw * 128);
    const u32 rswz = (u32)((padw & 7) << 4);
    const u32 coff = (u32)((h & 3) * 32);
    *(uint4*)(dst + rowb + ((coff +  0) ^ rswz)) = make_uint4(ph[0], ph[1], ph[2], ph[3]);
    *(uint4*)(dst + rowb + ((coff + 16) ^ rswz)) = make_uint4(ph[4], ph[5], ph[6], ph[7]);
}

// ---------------------------------------------------------------------------
// Fused gates + LayerNorm + final LSTM update (float4).
//   c_pre = sig(cf)*c_cur + sig(ci)*tanh(cg)   (was gates_kernel)
//   c = c_pre + sig(a)*tanh(LN(outp));  h = sig(o)*tanh(c)
// ---------------------------------------------------------------------------
__global__ void __launch_bounds__(512)
ln_final(const float* __restrict__ c_cur,
         const float* __restrict__ norm_w, const float* __restrict__ norm_b,
         float* __restrict__ d_out)
{
    const int b   = blockIdx.x;
    const int tid = threadIdx.x;
    const float4* p4 = (const float4*)(g_outp + (size_t)b * 32768);

    float s = 0.0f, s2 = 0.0f;
    for (int f = tid; f < 8192; f += 512) {
        const float4 v = p4[f];
        s += v.x + v.y + v.z + v.w;
        s2 = fmaf(v.x, v.x, s2); s2 = fmaf(v.y, v.y, s2);
        s2 = fmaf(v.z, v.z, s2); s2 = fmaf(v.w, v.w, s2);
    }
#pragma unroll
    for (int off = 16; off > 0; off >>= 1) {
        s  += __shfl_down_sync(0xffffffffu, s, off);
        s2 += __shfl_down_sync(0xffffffffu, s2, off);
    }
    __shared__ float rs_[16], rs2_[16];
    __shared__ float sh_mu, sh_rs;
    if ((tid & 31) == 0) { rs_[tid >> 5] = s; rs2_[tid >> 5] = s2; }
    __syncthreads();
    if (tid == 0) {
        float ts = 0.0f, ts2 = 0.0f;
#pragma unroll
        for (int w = 0; w < 16; w++) { ts += rs_[w]; ts2 += rs2_[w]; }
        const float mu  = ts * (1.0f / 32768.0f);
        const float var = ts2 * (1.0f / 32768.0f) - mu * mu;
        sh_mu = mu;
        sh_rs = rsqrtf(var + 1e-5f);
    }
    __syncthreads();

    const float mu = sh_mu, rs = sh_rs;
    const float4* cc4 = (const float4*)(g_cc + (size_t)b * 640 * HW);
    const float4* cu4 = (const float4*)(c_cur + (size_t)b * 32768);
    const float4* nw4 = (const float4*)norm_w;
    const float4* nb4 = (const float4*)norm_b;
    float4* dc = (float4*)(d_out + OFF_C + (size_t)b * 32768);
    float4* dh = (float4*)(d_out + OFF_H + (size_t)b * 32768);
    for (int f = tid; f < 8192; f += 512) {
        const float4 pv = p4[f];
        const float4 wv = nw4[f], bv = nb4[f];
        const float4 iv = cc4[f];            // gate i
        const float4 fv = cc4[f + 8192];     // gate f
        const float4 ov = cc4[f + 16384];    // gate o
        const float4 gv = cc4[f + 24576];    // gate g
        const float4 av = cc4[f + 32768];    // gate a
        const float4 cu = cu4[f];
        float4 cv, hv;
        { const float ln = (pv.x - mu) * rs * wv.x + bv.x;
          cv.x = sigmoidf_(fv.x) * cu.x + sigmoidf_(iv.x) * tanhf(gv.x)
               + sigmoidf_(av.x) * tanhf(ln);
          hv.x = sigmoidf_(ov.x) * tanhf(cv.x); }
        { const float ln = (pv.y - mu) * rs * wv.y + bv.y;
          cv.y = sigmoidf_(fv.y) * cu.y + sigmoidf_(iv.y) * tanhf(gv.y)
               + sigmoidf_(av.y) * tanhf(ln);
          hv.y = sigmoidf_(ov.y) * tanhf(cv.y); }
        { const float ln = (pv.z - mu) * rs * wv.z + bv.z;
          cv.z = sigmoidf_(fv.z) * cu.z + sigmoidf_(iv.z) * tanhf(gv.z)
               + sigmoidf_(av.z) * tanhf(ln);
          hv.z = sigmoidf_(ov.z) * tanhf(cv.z); }
        { const float ln = (pv.w - mu) * rs * wv.w + bv.w;
          cv.w = sigmoidf_(fv.w) * cu.w + sigmoidf_(iv.w) * tanhf(gv.w)
               + sigmoidf_(av.w) * tanhf(ln);
          hv.w = sigmoidf_(ov.w) * tanhf(cv.w); }
        dc[f] = cv;
        dh[f] = hv;
    }
}

// ---------------------------------------------------------------------------
// Launch — R13 topology (proven best):
//   s0: prep_in -> [fork] -> prep_w(main) -> main conv -> (wait join) -> ln
//   sB: wait(fork) -> prep_w(proj), prep_w(out) -> proj -> attn -> out -> [join]
// ---------------------------------------------------------------------------
extern "C" void kernel_launch(void* const* d_in, const int* in_sizes, int n_in,
                              void* d_out_v, int out_size)
{
    const float* input    = (const float*)d_in[0];
    const float* h_cur    = (const float*)d_in[1];
    const float* c_cur    = (const float*)d_in[2];
    const float* concat_k = (const float*)d_in[3];
    const float* concat_v = (const float*)d_in[4];
    const unsigned int* attn_mask = (const unsigned int*)d_in[5];
    const float* main_w   = (const float*)d_in[6];
    const float* main_b   = (const float*)d_in[7];
    const float* proj_w   = (const float*)d_in[8];
    const float* proj_b   = (const float*)d_in[9];
    const float* out_w    = (const float*)d_in[10];
    const float* out_b    = (const float*)d_in[11];
    const float* norm_w   = (const float*)d_in[12];
    const float* norm_b   = (const float*)d_in[13];
    const float* pos_w    = (const float*)d_in[14];
    const float* pos_b    = (const float*)d_in[15];
    float* d_out = (float*)d_out_v;

    cudaFuncSetAttribute(conv_mma<4,0>, cudaFuncAttributeMaxDynamicSharedMemorySize, CONV_SMEM);
    cudaFuncSetAttribute(conv_mma<2,1>, cudaFuncAttributeMaxDynamicSharedMemorySize, CONV_SMEM);
    cudaFuncSetAttribute(conv_mma<2,2>, cudaFuncAttributeMaxDynamicSharedMemorySize, CONV_SMEM);

    __half *wm, *wp, *wo;
    char *bin_p, *battn_p;
    cudaGetSymbolAddress((void**)&wm, g_wm);
    cudaGetSymbolAddress((void**)&wp, g_wp);
    cudaGetSymbolAddress((void**)&wo, g_wo);
    cudaGetSymbolAddress((void**)&bin_p, g_bin);
    cudaGetSymbolAddress((void**)&battn_p, g_battn);

    cudaStream_t s0 = 0;
    cudaStream_t sB = g_res.sB;

    // ---- shared input prep (needed by main + proj) ----
    prep_in<<<dim3(16, BATCH), 256, 0, s0>>>(input, h_cur);

    // ---- fork ----
    cudaEventRecord(g_res.evFork, s0);
    cudaStreamWaitEvent(sB, g_res.evFork, 0);

    // ---- chain B (sB): proj weights+conv -> attn -> out conv ----
    prep_w<1><<<(108 * 2048) / 256, 256, 0, sB>>>(proj_w, 108, 2);
    prep_w<2><<<( 36 * 2048) / 256, 256, 0, sB>>>(out_w,   36, 2);
    conv_mma<2,1><<<dim3(6, BATCH), 256, CONV_SMEM, sB>>>(
        wp, bin_p, 4, proj_b, nullptr, pos_w, d_out);
    attn_fused<<<BH, 256, 0, sB>>>(concat_k, concat_v, attn_mask, pos_w, pos_b,
                                   d_out + OFF_K, d_out + OFF_V);
    conv_mma<2,2><<<dim3(2, BATCH), 256, CONV_SMEM, sB>>>(
        wo, battn_p, 2, out_b, input, nullptr, d_out);

    // ---- chain A (s0): main weights+conv ----
    prep_w<0><<<(360 * 2048) / 256, 256, 0, s0>>>(main_w, 360, 4);
    conv_mma<4,0><<<dim3(10, BATCH), 256, CONV_SMEM, s0>>>(
        wm, bin_p, 4, main_b, nullptr, nullptr, d_out);

    // ---- join ----
    cudaEventRecord(g_res.evJoin, sB);
    cudaStreamWaitEvent(s0, g_res.evJoin, 0);

    // ---- fused gates + LayerNorm + final LSTM update ----
    ln_final<<<BATCH, 512, 0, s0>>>(c_cur, norm_w, norm_b, d_out);
}